// round 2
// baseline (speedup 1.0000x reference)
#include <cuda_runtime.h>
#include <math.h>

#define SEQ 512
#define BSZ 128
#define NI  1024
#define NH  1024

// Double-buffered hidden state + grid barrier state (no allocations allowed)
__device__ float g_hbuf[2][BSZ * NH];
__device__ unsigned g_count = 0;
__device__ unsigned g_gen = 0;

__device__ __forceinline__ void grid_sync(unsigned nblk) {
    __syncthreads();
    if (threadIdx.x == 0) {
        __threadfence();
        unsigned gen = g_gen;
        if (atomicAdd(&g_count, 1u) == nblk - 1u) {
            g_count = 0;
            __threadfence();
            atomicAdd(&g_gen, 1u);
        } else {
            while (*((volatile unsigned*)&g_gen) == gen) { }
            __threadfence();
        }
    }
    __syncthreads();
}

__device__ __forceinline__ float sigmoidf_(float v) {
    return 1.0f / (1.0f + expf(-v));
}

// One persistent kernel runs the whole recurrence.
// Grid: (NH/16, BSZ/64) = (64, 2) = 128 blocks, 256 threads each.
// Block (nx, my): batch rows [my*64, my*64+64), h-cols [nx*16, nx*16+16),
// all 4 gates. GEMM tile 64(m) x 64(gate-rows) x K=2048 (x-half + h-half).
// Thread (ty,tx): 4 batch rows x 4 gates for h-col nx*16+tx; c kept in regs.
__global__ void __launch_bounds__(256, 1)
lstm_persistent_kernel(const float* __restrict__ x,
                       const float* __restrict__ w_ih,
                       const float* __restrict__ w_hh,
                       const float* __restrict__ b_ih,
                       const float* __restrict__ b_hh,
                       float* __restrict__ out)
{
    __shared__ float As[16][68];   // [k][m_local], padded
    __shared__ float Bs[16][68];   // [k][gate*16+col], padded

    const int tid = threadIdx.x;         // 0..255
    const int tx  = tid & 15;            // h-col within tile
    const int ty  = tid >> 4;            // batch-row group
    const int nh0 = blockIdx.x * 16;     // h-col tile base
    const int m0  = blockIdx.y * 64;     // batch tile base
    const unsigned nblk = gridDim.x * gridDim.y;  // 128

    // Loader mapping: 256 threads load 64 rows x 16 k (one float4 each)
    const int lrow  = tid >> 2;          // 0..63
    const int lseg  = tid & 3;           // k offset = lseg*4
    const int lgate = lrow >> 4;         // 0..3
    const int lcol  = lrow & 15;         // 0..15
    const int brow  = lgate * NH + nh0 + lcol;   // weight row for B loads

    // Combined biases for this thread's 4 gates (fixed h-col)
    float bc[4];
#pragma unroll
    for (int g = 0; g < 4; g++) {
        const int r = g * NH + nh0 + tx;
        bc[g] = b_ih[r] + b_hh[r];
    }

    float c[4] = {0.f, 0.f, 0.f, 0.f};   // cell state: register-resident
    const int hcol = nh0 + tx;

    for (int s = 0; s < SEQ; s++) {
        float acc[4][4];
#pragma unroll
        for (int i = 0; i < 4; i++)
#pragma unroll
            for (int g = 0; g < 4; g++) acc[i][g] = 0.0f;

        const float* xs    = x + (size_t)s * BSZ * NI;
        const float* hprev = g_hbuf[s & 1];
        const int ktEnd = (s == 0) ? 64 : 128;   // h0 == 0: skip recurrent half

        for (int kt = 0; kt < ktEnd; kt++) {
            const int k0 = kt * 16;
            float4 av, bv;
            if (kt < 64) {
                av = *(const float4*)(xs + (size_t)(m0 + lrow) * NI + k0 + lseg * 4);
                bv = *(const float4*)(w_ih + (size_t)brow * NI + k0 + lseg * 4);
            } else {
                const int kk = k0 - NI;
                // h written by other SMs this/last step: bypass L1 (persistent kernel!)
                av = __ldcg((const float4*)(hprev + (size_t)(m0 + lrow) * NH + kk + lseg * 4));
                bv = *(const float4*)(w_hh + (size_t)brow * NH + kk + lseg * 4);
            }

            __syncthreads();   // previous tile's compute done before overwrite
            As[lseg * 4 + 0][lrow] = av.x;
            As[lseg * 4 + 1][lrow] = av.y;
            As[lseg * 4 + 2][lrow] = av.z;
            As[lseg * 4 + 3][lrow] = av.w;
            Bs[lseg * 4 + 0][lrow] = bv.x;
            Bs[lseg * 4 + 1][lrow] = bv.y;
            Bs[lseg * 4 + 2][lrow] = bv.z;
            Bs[lseg * 4 + 3][lrow] = bv.w;
            __syncthreads();

#pragma unroll
            for (int k = 0; k < 16; k++) {
                float4 a = *(const float4*)&As[k][ty * 4];
                float ar[4] = {a.x, a.y, a.z, a.w};
                float br[4];
                br[0] = Bs[k][0 * 16 + tx];
                br[1] = Bs[k][1 * 16 + tx];
                br[2] = Bs[k][2 * 16 + tx];
                br[3] = Bs[k][3 * 16 + tx];
#pragma unroll
                for (int i = 0; i < 4; i++)
#pragma unroll
                    for (int g = 0; g < 4; g++)
                        acc[i][g] = fmaf(ar[i], br[g], acc[i][g]);
            }
        }

        // Fused pointwise LSTM cell update (register-local)
        float* hnext = g_hbuf[(s + 1) & 1];
#pragma unroll
        for (int i = 0; i < 4; i++) {
            const int b = m0 + ty * 4 + i;
            const float ig = sigmoidf_(acc[i][0] + bc[0]);
            const float fg = sigmoidf_(acc[i][1] + bc[1]);
            const float gg = tanhf(acc[i][2] + bc[2]);
            const float og = sigmoidf_(acc[i][3] + bc[3]);
            const float cv = fg * c[i] + ig * gg;
            c[i] = cv;
            const float hv = og * tanhf(cv);
            hnext[(size_t)b * NH + hcol] = hv;
            out[((size_t)s * BSZ + b) * NH + hcol] = hv;
            if (s == SEQ - 1) {
                out[((size_t)SEQ * BSZ + b) * NH + hcol] = hv;              // hN
                out[((size_t)(SEQ * BSZ + BSZ) + b) * NH + hcol] = cv;      // cN
            }
        }

        grid_sync(nblk);   // h(s+1) visible to all before next step reads it
    }
}

extern "C" void kernel_launch(void* const* d_in, const int* in_sizes, int n_in,
                              void* d_out, int out_size)
{
    const float* x    = (const float*)d_in[0];
    const float* w_ih = (const float*)d_in[1];
    const float* w_hh = (const float*)d_in[2];
    const float* b_ih = (const float*)d_in[3];
    const float* b_hh = (const float*)d_in[4];
    float* out = (float*)d_out;

    dim3 grid(NH / 16, BSZ / 64);   // (64, 2) = 128 blocks, all co-resident
    lstm_persistent_kernel<<<grid, 256>>>(x, w_ih, w_hh, b_ih, b_hh, out);
}

// round 3
// speedup vs baseline: 1.1178x; 1.1178x over previous
#include <cuda_runtime.h>
#include <math.h>

#define SEQ 512
#define BSZ 128
#define NI  1024
#define NH  1024
#define BK  32

// Persistent state (no allocations allowed)
__device__ float g_hbuf[2][BSZ * NH];
__device__ unsigned g_count = 0;
__device__ unsigned g_gen = 0;

__device__ __forceinline__ void grid_sync(unsigned nblk) {
    __syncthreads();
    if (threadIdx.x == 0) {
        __threadfence();
        unsigned gen = g_gen;
        if (atomicAdd(&g_count, 1u) == nblk - 1u) {
            g_count = 0;
            __threadfence();
            atomicAdd(&g_gen, 1u);
        } else {
            while (*((volatile unsigned*)&g_gen) == gen) { }
            __threadfence();
        }
    }
    __syncthreads();
}

__device__ __forceinline__ float sigmoidf_(float v) {
    return 1.0f / (1.0f + expf(-v));
}

// Packed fp32x2 helpers (Blackwell FFMA2 — only reachable via PTX)
__device__ __forceinline__ unsigned long long dup_f32(float v) {
    unsigned long long r;
    unsigned u = __float_as_uint(v);
    asm("mov.b64 %0, {%1, %1};" : "=l"(r) : "r"(u));
    return r;
}
__device__ __forceinline__ void ffma2(unsigned long long& acc,
                                      unsigned long long a,
                                      unsigned long long b) {
    asm("fma.rn.f32x2 %0, %1, %2, %0;" : "+l"(acc) : "l"(a), "l"(b));
}
__device__ __forceinline__ float2 unpack_f32x2(unsigned long long p) {
    unsigned lo, hi;
    asm("mov.b64 {%0, %1}, %2;" : "=r"(lo), "=r"(hi) : "l"(p));
    return make_float2(__uint_as_float(lo), __uint_as_float(hi));
}

// Persistent kernel. Grid = 128 blocks x 256 threads (all co-resident).
// Block b: all 128 batch rows x 8 h-cols [b*8, b*8+8) x all 4 gates.
// GEMM tile 128(M) x 32(N=8cols*4gates) x K=2048 (x-half then h-half), BK=32.
// Thread (ty,tx): 4 batch rows (ty*4..) x 4 gates of h-col tx; packed-pair
// accumulators over gate pairs (i,f) and (g,o); c register-resident.
__global__ void __launch_bounds__(256, 1)
lstm_persistent_kernel(const float* __restrict__ x,
                       const float* __restrict__ w_ih,
                       const float* __restrict__ w_hh,
                       const float* __restrict__ b_ih,
                       const float* __restrict__ b_hh,
                       float* __restrict__ out)
{
    __shared__ float As[2][BK][132];   // [buf][k][m], padded
    __shared__ float Bs[2][BK][36];    // [buf][k][col*4+gate], padded

    const int tid = threadIdx.x;
    const int tx  = tid & 7;             // h-col within tile (0..7)
    const int ty  = tid >> 3;            // 0..31 -> batch rows ty*4..ty*4+3
    const int nh0 = blockIdx.x * 8;
    const unsigned nblk = gridDim.x;     // 128

    // A loader: thread covers row am, 16 consecutive k (aseg half of BK)
    const int am   = tid >> 1;           // 0..127
    const int aseg = (tid & 1) * 16;     // 0 or 16
    // B loader: thread covers colgate bcg, 4 consecutive k
    const int bcg  = tid & 31;           // dest index col*4+gate
    const int bkq  = tid >> 5;           // 0..7 -> k = bkq*4..bkq*4+3
    const int bgrow = (bcg & 3) * NH + nh0 + (bcg >> 2);   // weight row

    const int hcol = nh0 + tx;
    float bc[4];
#pragma unroll
    for (int g = 0; g < 4; g++)
        bc[g] = b_ih[g * NH + hcol] + b_hh[g * NH + hcol];

    float c[4] = {0.f, 0.f, 0.f, 0.f};

    float4 rA[4];
    float4 rB;

    // Prefetch step 0, tile 0 (x-half)
    {
        const float* ab = x + (size_t)am * NI + aseg;
        rA[0] = *(const float4*)(ab + 0);
        rA[1] = *(const float4*)(ab + 4);
        rA[2] = *(const float4*)(ab + 8);
        rA[3] = *(const float4*)(ab + 12);
        rB    = *(const float4*)(w_ih + (size_t)bgrow * NI + bkq * 4);
    }

    for (int s = 0; s < SEQ; s++) {
        const float* xs    = x + (size_t)s * BSZ * NI;
        const float* hprev = g_hbuf[s & 1];
        const int ktEnd = (s == 0) ? 32 : 64;   // h0 == 0: skip recurrent half

        unsigned long long acc[4][2];
#pragma unroll
        for (int i = 0; i < 4; i++) { acc[i][0] = 0ull; acc[i][1] = 0ull; }

        for (int kt = 0; kt < ktEnd; kt++) {
            const int buf = kt & 1;

            // Store prefetched tile to SMEM
#pragma unroll
            for (int q = 0; q < 4; q++) {
                As[buf][aseg + q * 4 + 0][am] = rA[q].x;
                As[buf][aseg + q * 4 + 1][am] = rA[q].y;
                As[buf][aseg + q * 4 + 2][am] = rA[q].z;
                As[buf][aseg + q * 4 + 3][am] = rA[q].w;
            }
            Bs[buf][bkq * 4 + 0][bcg] = rB.x;
            Bs[buf][bkq * 4 + 1][bcg] = rB.y;
            Bs[buf][bkq * 4 + 2][bcg] = rB.z;
            Bs[buf][bkq * 4 + 3][bcg] = rB.w;
            __syncthreads();

            // Prefetch next tile (hidden behind compute)
            if (kt + 1 < ktEnd) {
                const int nk = kt + 1;
                if (nk < 32) {
                    const float* ab = xs + (size_t)am * NI + nk * BK + aseg;
                    rA[0] = *(const float4*)(ab + 0);
                    rA[1] = *(const float4*)(ab + 4);
                    rA[2] = *(const float4*)(ab + 8);
                    rA[3] = *(const float4*)(ab + 12);
                    rB = *(const float4*)(w_ih + (size_t)bgrow * NI + nk * BK + bkq * 4);
                } else {
                    const int ko = (nk - 32) * BK;
                    const float* ab = hprev + (size_t)am * NH + ko + aseg;
                    // h written by other SMs: bypass L1
                    rA[0] = __ldcg((const float4*)(ab + 0));
                    rA[1] = __ldcg((const float4*)(ab + 4));
                    rA[2] = __ldcg((const float4*)(ab + 8));
                    rA[3] = __ldcg((const float4*)(ab + 12));
                    rB = *(const float4*)(w_hh + (size_t)bgrow * NH + ko + bkq * 4);
                }
            } else if (s + 1 < SEQ) {
                // First tile of next step is x-half: prefetch across the grid sync
                const float* ab = xs + (size_t)BSZ * NI + (size_t)am * NI + aseg;
                rA[0] = *(const float4*)(ab + 0);
                rA[1] = *(const float4*)(ab + 4);
                rA[2] = *(const float4*)(ab + 8);
                rA[3] = *(const float4*)(ab + 12);
                rB = *(const float4*)(w_ih + (size_t)bgrow * NI + bkq * 4);
            }

            // Compute on current buffer: 32 k-iters x 8 FFMA2
#pragma unroll
            for (int k = 0; k < BK; k++) {
                float4 a = *(const float4*)&As[buf][k][ty * 4];
                unsigned long long bp0 = *(const unsigned long long*)&Bs[buf][k][tx * 4];
                unsigned long long bp1 = *(const unsigned long long*)&Bs[buf][k][tx * 4 + 2];
                unsigned long long a0 = dup_f32(a.x);
                unsigned long long a1 = dup_f32(a.y);
                unsigned long long a2 = dup_f32(a.z);
                unsigned long long a3 = dup_f32(a.w);
                ffma2(acc[0][0], a0, bp0); ffma2(acc[0][1], a0, bp1);
                ffma2(acc[1][0], a1, bp0); ffma2(acc[1][1], a1, bp1);
                ffma2(acc[2][0], a2, bp0); ffma2(acc[2][1], a2, bp1);
                ffma2(acc[3][0], a3, bp0); ffma2(acc[3][1], a3, bp1);
            }
        }

        // Fused LSTM cell update (register-local)
        float* hnext = g_hbuf[(s + 1) & 1];
#pragma unroll
        for (int i = 0; i < 4; i++) {
            const int m = ty * 4 + i;
            float2 vif = unpack_f32x2(acc[i][0]);   // (i, f) gates
            float2 vgo = unpack_f32x2(acc[i][1]);   // (g, o) gates
            const float ig = sigmoidf_(vif.x + bc[0]);
            const float fg = sigmoidf_(vif.y + bc[1]);
            const float gg = tanhf(vgo.x + bc[2]);
            const float og = sigmoidf_(vgo.y + bc[3]);
            const float cv = fg * c[i] + ig * gg;
            c[i] = cv;
            const float hv = og * tanhf(cv);
            hnext[(size_t)m * NH + hcol] = hv;
            out[((size_t)s * BSZ + m) * NH + hcol] = hv;
            if (s == SEQ - 1) {
                out[((size_t)SEQ * BSZ + m) * NH + hcol] = hv;               // hN
                out[((size_t)(SEQ * BSZ + BSZ) + m) * NH + hcol] = cv;       // cN
            }
        }

        grid_sync(nblk);   // h(s+1) visible chip-wide before next step reads it
    }
}

extern "C" void kernel_launch(void* const* d_in, const int* in_sizes, int n_in,
                              void* d_out, int out_size)
{
    const float* x    = (const float*)d_in[0];
    const float* w_ih = (const float*)d_in[1];
    const float* w_hh = (const float*)d_in[2];
    const float* b_ih = (const float*)d_in[3];
    const float* b_hh = (const float*)d_in[4];
    float* out = (float*)d_out;

    lstm_persistent_kernel<<<128, 256>>>(x, w_ih, w_hh, b_ih, b_hh, out);
}